// round 10
// baseline (speedup 1.0000x reference)
#include <cuda_runtime.h>
#include <cstdint>

#define B 512
#define T 2048
#define K 32
#define CH 32            // time steps per staged chunk
#define NCH (T / CH)     // 64 chunks
#define WPC 2            // warps per CTA
#define CPW 2            // chains (batches) per warp
#define CHB (CH * K * 4) // 4096
#define FULL 0xffffffffu

#define POT_F (WPC * CPW * 2 * CH * K)
#define M_F   (WPC * CPW * 2 * CH * K)
#define SMEM_DYN_BYTES ((POT_F + M_F + K * K + WPC * CPW * K) * 4)

// m-trace; last 2 chunks per batch never hit gmem
__device__ float g_m[(size_t)B * T * K];

#define ADD2(out, a, b) asm("add.rn.f32x2 %0, %1, %2;" : "=l"(out) : "l"(a), "l"(b))
#define UNPK(lo, hi, v) asm("mov.b64 {%0, %1}, %2;" : "=f"(lo), "=f"(hi) : "l"(v))
#define WSYNC()         __syncwarp()

__device__ __forceinline__ void cp16(uint32_t saddr, const void* gptr) {
    asm volatile("cp.async.cg.shared.global [%0], [%1], 16;" :: "r"(saddr), "l"(gptr));
}
#define CP_COMMIT()  asm volatile("cp.async.commit_group;")
#define CP_WAIT(n)   asm volatile("cp.async.wait_group %0;" :: "n"(n))

__device__ __forceinline__ void bulk_s2g(void* gdst, uint32_t ssrc, uint32_t bytes) {
    asm volatile("cp.async.bulk.global.shared::cta.bulk_group [%0], [%1], %2;"
                 :: "l"(gdst), "r"(ssrc), "r"(bytes) : "memory");
}
#define BULK_COMMIT()    asm volatile("cp.async.bulk.commit_group;")
#define BULK_WAIT_RD(n)  asm volatile("cp.async.bulk.wait_group.read %0;" :: "n"(n))
#define BULK_WAIT(n)     asm volatile("cp.async.bulk.wait_group %0;" :: "n"(n))
#define FENCE_ASYNC()    asm volatile("fence.proxy.async.shared::cta;" ::: "memory")

__global__ void __launch_bounds__(WPC * 32, 1) crf_viterbi_kernel(
    const float* __restrict__ pot,     // [B, T, K]
    const float* __restrict__ trans,   // [K, K]
    float* __restrict__ out)           // [B, T, K] one-hot
{
    extern __shared__ __align__(16) float dyn[];
    float* potBase = dyn;                       // [WPC][CPW][2][CH*K]
    float* mBase   = dyn + POT_F;
    float* trColS  = mBase + M_F;               // trColS[j*K+i] = trans[i][j]
    float* stBase  = trColS + K * K;            // [WPC][CPW][K]

    const int lane = threadIdx.x & 31;
    const int w    = threadIdx.x >> 5;
    const int b0   = (blockIdx.x * WPC + w) * CPW;

    const char* pB0 = (const char*)(pot + (size_t)b0 * T * K);
    const char* pB1 = (const char*)(pot + (size_t)(b0 + 1) * T * K);
    const char* mB0 = (const char*)(g_m + (size_t)b0 * T * K);
    const char* mB1 = (const char*)(g_m + (size_t)(b0 + 1) * T * K);
    float* ob0 = out + (size_t)b0 * T * K + lane;
    float* ob1 = out + (size_t)(b0 + 1) * T * K + lane;

    float* p00 = potBase + ((w * CPW + 0) * 2 + 0) * CH * K;   // chain0 buf0
    float* p01 = potBase + ((w * CPW + 0) * 2 + 1) * CH * K;   // chain0 buf1
    float* p10 = potBase + ((w * CPW + 1) * 2 + 0) * CH * K;   // chain1 buf0
    float* p11 = potBase + ((w * CPW + 1) * 2 + 1) * CH * K;
    float* m00 = mBase + ((w * CPW + 0) * 2 + 0) * CH * K;
    float* m01 = mBase + ((w * CPW + 0) * 2 + 1) * CH * K;
    float* m10 = mBase + ((w * CPW + 1) * 2 + 0) * CH * K;
    float* m11 = mBase + ((w * CPW + 1) * 2 + 1) * CH * K;
    float* st0 = stBase + (w * CPW + 0) * K;
    float* st1 = stBase + (w * CPW + 1) * K;

    const uint32_t pA00 = (uint32_t)__cvta_generic_to_shared(p00);
    const uint32_t pA01 = (uint32_t)__cvta_generic_to_shared(p01);
    const uint32_t pA10 = (uint32_t)__cvta_generic_to_shared(p10);
    const uint32_t pA11 = (uint32_t)__cvta_generic_to_shared(p11);
    const uint32_t mA00 = (uint32_t)__cvta_generic_to_shared(m00);
    const uint32_t mA01 = (uint32_t)__cvta_generic_to_shared(m01);
    const uint32_t mA10 = (uint32_t)__cvta_generic_to_shared(m10);
    const uint32_t mA11 = (uint32_t)__cvta_generic_to_shared(m11);

    // packed transition column `lane` (shared by both chains)
    unsigned long long tj2[16];
#pragma unroll
    for (int q = 0; q < 16; q++) {
        float lo = __ldg(trans + (2 * q) * K + lane);
        float hi = __ldg(trans + (2 * q + 1) * K + lane);
        asm("mov.b64 %0, {%1, %2};" : "=l"(tj2[q]) : "f"(lo), "f"(hi));
    }
    if (w == 0) {
#pragma unroll
        for (int i = 0; i < K; i++) trColS[lane * K + i] = trans[i * K + lane];
    }
    __syncthreads();

// stage pot chunk `c` of both chains into buffers (db0, db1): 8 cp16 per chain
#define STAGE_POT(c, db0, db1) do {                                            \
        const char* s0_ = pB0 + (size_t)(c) * CHB;                             \
        const char* s1_ = pB1 + (size_t)(c) * CHB;                             \
        _Pragma("unroll")                                                      \
        for (int i = 0; i < 8; i++) cp16((db0) + lane*16 + i*512, s0_ + lane*16 + i*512); \
        _Pragma("unroll")                                                      \
        for (int i = 0; i < 8; i++) cp16((db1) + lane*16 + i*512, s1_ + lane*16 + i*512); \
    } while (0)

    // ---- stage forward chunks 0 and 1 for both chains ----
    STAGE_POT(0, pA00, pA10); CP_COMMIT();
    STAGE_POT(1, pA01, pA11); CP_COMMIT();
    CP_WAIT(1);
    WSYNC();

    float s0 = p00[lane], s1 = p10[lane];       // s(0)
    const float pot0_0 = s0, pot0_1 = s1;
    float mlast0 = 0.0f, mlast1 = 0.0f;

// one forward DP step for BOTH chains (independent -> ILP hides chain latency)
#define FSTEP2(r, pc0, pc1, mr0, mr1) do {                                     \
        const float pcur0 = (pc0)[(r) * K + lane];                             \
        const float pcur1 = (pc1)[(r) * K + lane];                             \
        st0[lane] = s0;  st1[lane] = s1;                                       \
        const ulonglong2* sp0 = (const ulonglong2*)st0;                        \
        const ulonglong2* sp1 = (const ulonglong2*)st1;                        \
        unsigned long long a2[16], b2[16];                                     \
        _Pragma("unroll")                                                      \
        for (int q = 0; q < 8; q++) {                                          \
            ulonglong2 ra = sp0[q];                                            \
            ADD2(a2[2*q],   ra.x, tj2[2*q]);                                   \
            ADD2(a2[2*q+1], ra.y, tj2[2*q+1]);                                 \
            ulonglong2 rb = sp1[q];                                            \
            ADD2(b2[2*q],   rb.x, tj2[2*q]);                                   \
            ADD2(b2[2*q+1], rb.y, tj2[2*q+1]);                                 \
        }                                                                      \
        float am[16], bm[16];                                                  \
        _Pragma("unroll")                                                      \
        for (int q = 0; q < 16; q++) {                                         \
            float lo, hi;                                                      \
            UNPK(lo, hi, a2[q]); am[q] = fmaxf(lo, hi);                        \
            UNPK(lo, hi, b2[q]); bm[q] = fmaxf(lo, hi);                        \
        }                                                                      \
        _Pragma("unroll")                                                      \
        for (int q = 0; q < 8; q++) { am[q] = fmaxf(am[2*q], am[2*q+1]);       \
                                      bm[q] = fmaxf(bm[2*q], bm[2*q+1]); }     \
        _Pragma("unroll")                                                      \
        for (int q = 0; q < 4; q++) { am[q] = fmaxf(am[2*q], am[2*q+1]);       \
                                      bm[q] = fmaxf(bm[2*q], bm[2*q+1]); }     \
        const float ma = fmaxf(fmaxf(am[0], am[1]), fmaxf(am[2], am[3]));      \
        const float mb = fmaxf(fmaxf(bm[0], bm[1]), fmaxf(bm[2], bm[3]));      \
        (mr0)[(r) * K + lane] = ma;                                            \
        (mr1)[(r) * K + lane] = mb;                                            \
        s0 = ma + pcur0;  s1 = mb + pcur1;                                     \
        mlast0 = ma;      mlast1 = mb;                                         \
    } while (0)

    // ================= forward =================
    // chunk 0 (rows 1..CH-1), peeled
    {
#pragma unroll 4
        for (int r = 1; r < CH; r++) FSTEP2(r, p00, p10, m00, m10);
        WSYNC();
        FENCE_ASYNC();
        if (lane == 0) {
            bulk_s2g((void*)mB0, mA00, CHB);
            bulk_s2g((void*)mB1, mA10, CHB);
            BULK_COMMIT();
            BULK_WAIT_RD(1);
        }
        STAGE_POT(2, pA00, pA10);
        CP_COMMIT();
        CP_WAIT(1);
        WSYNC();
    }
    for (int c = 1; c < NCH; c++) {
        const float* pc0 = (c & 1) ? p01 : p00;
        const float* pc1 = (c & 1) ? p11 : p10;
        float* mr0 = (c & 1) ? m01 : m00;
        float* mr1 = (c & 1) ? m11 : m10;
#pragma unroll 4
        for (int r = 0; r < CH; r++) FSTEP2(r, pc0, pc1, mr0, mr1);
        WSYNC();
        if (c <= NCH - 3) {
            FENCE_ASYNC();
            if (lane == 0) {
                bulk_s2g((void*)(mB0 + (size_t)c * CHB), (c & 1) ? mA01 : mA00, CHB);
                bulk_s2g((void*)(mB1 + (size_t)c * CHB), (c & 1) ? mA11 : mA10, CHB);
                BULK_COMMIT();
                BULK_WAIT_RD(1);
            }
        }
        if (c + 2 < NCH) {
            STAGE_POT(c + 2, ((c & 1) == 0) ? pA00 : pA01, ((c & 1) == 0) ? pA10 : pA11);
            CP_COMMIT();
            CP_WAIT(1);
            WSYNC();
        } else if (c + 1 < NCH) {
            CP_WAIT(0);
            WSYNC();
        }
    }

    // ---- final tags ----
    float mm0 = s0, mm1 = s1;
#pragma unroll
    for (int off = 16; off; off >>= 1) {
        mm0 = fmaxf(mm0, __shfl_xor_sync(FULL, mm0, off));
        mm1 = fmaxf(mm1, __shfl_xor_sync(FULL, mm1, off));
    }
    int tag0 = __ffs(__ballot_sync(FULL, s0 == mm0)) - 1;
    int tag1 = __ffs(__ballot_sync(FULL, s1 == mm1)) - 1;
    ob0[(size_t)(T - 1) * K] = (lane == tag0) ? 1.0f : 0.0f;
    ob1[(size_t)(T - 1) * K] = (lane == tag1) ? 1.0f : 0.0f;

    if (lane == 0) BULK_WAIT(0);
    WSYNC();

    // ================= backtrack (last 2 chunks resident) =================
    float mcur0 = mlast0, mcur1 = mlast1;

#define BSTEP2(tp, r, mc0, pc0, mc1, pc1) do {                                 \
        const float tgt0 = __shfl_sync(FULL, mcur0, tag0);                     \
        const float tgt1 = __shfl_sync(FULL, mcur1, tag1);                     \
        const float tv0 = trColS[tag0 * K + lane];                             \
        const float tv1 = trColS[tag1 * K + lane];                             \
        const float mp0 = (mc0)[(r) * K + lane];                               \
        const float mp1 = (mc1)[(r) * K + lane];                               \
        const float pp0 = (pc0)[(r) * K + lane];                               \
        const float pp1 = (pc1)[(r) * K + lane];                               \
        const float v0 = (mp0 + pp0) + tv0;                                    \
        const float v1 = (mp1 + pp1) + tv1;                                    \
        const unsigned k0 = __ballot_sync(FULL, v0 == tgt0);                   \
        const unsigned k1 = __ballot_sync(FULL, v1 == tgt1);                   \
        tag0 = __ffs(k0) - 1;  tag1 = __ffs(k1) - 1;                           \
        ob0[(size_t)(tp) * K] = (lane == tag0) ? 1.0f : 0.0f;                  \
        ob1[(size_t)(tp) * K] = (lane == tag1) ? 1.0f : 0.0f;                  \
        mcur0 = mp0;  mcur1 = mp1;                                             \
    } while (0)

// stage m+pot chunk (c-2) of both chains into parity buffers of (c)
#define STAGE_BT(c) do {                                                       \
        const uint32_t md0 = (((c) & 1) == 0) ? mA00 : mA01;                   \
        const uint32_t md1 = (((c) & 1) == 0) ? mA10 : mA11;                   \
        const uint32_t pd0 = (((c) & 1) == 0) ? pA00 : pA01;                   \
        const uint32_t pd1 = (((c) & 1) == 0) ? pA10 : pA11;                   \
        const char* gm0 = mB0 + (size_t)((c) - 2) * CHB;                       \
        const char* gm1 = mB1 + (size_t)((c) - 2) * CHB;                       \
        const char* gp0 = pB0 + (size_t)((c) - 2) * CHB;                       \
        const char* gp1 = pB1 + (size_t)((c) - 2) * CHB;                       \
        _Pragma("unroll")                                                      \
        for (int i = 0; i < 8; i++) {                                          \
            cp16(md0 + lane*16 + i*512, gm0 + lane*16 + i*512);                \
            cp16(md1 + lane*16 + i*512, gm1 + lane*16 + i*512);                \
            cp16(pd0 + lane*16 + i*512, gp0 + lane*16 + i*512);                \
            cp16(pd1 + lane*16 + i*512, gp1 + lane*16 + i*512);                \
        }                                                                      \
        CP_COMMIT();                                                           \
        CP_WAIT(1);                                                            \
        WSYNC();                                                               \
    } while (0)

    // chunk NCH-1 (buf 1): rows CH-2..0
    {
#pragma unroll 4
        for (int r = CH - 2; r >= 0; r--) BSTEP2((NCH - 1) * CH + r, r, m01, p01, m11, p11);
        STAGE_BT(NCH - 1);
    }
    for (int c = NCH - 2; c >= 1; c--) {
        const float* mc0 = (c & 1) ? m01 : m00;
        const float* mc1 = (c & 1) ? m11 : m10;
        const float* pc0 = (c & 1) ? p01 : p00;
        const float* pc1 = (c & 1) ? p11 : p10;
#pragma unroll 4
        for (int r = CH - 1; r >= 0; r--) BSTEP2(c * CH + r, r, mc0, pc0, mc1, pc1);
        if (c >= 2) {
            STAGE_BT(c);
        } else {
            CP_WAIT(0);
            WSYNC();
        }
    }
    // chunk 0: rows CH-1..1
    {
#pragma unroll 4
        for (int r = CH - 1; r >= 1; r--) BSTEP2(r, r, m00, p00, m10, p10);
    }
    // last step: t=1 -> tag(0)
    {
        const float tgt0 = __shfl_sync(FULL, mcur0, tag0);
        const float tgt1 = __shfl_sync(FULL, mcur1, tag1);
        const float v0 = pot0_0 + trColS[tag0 * K + lane];
        const float v1 = pot0_1 + trColS[tag1 * K + lane];
        tag0 = __ffs(__ballot_sync(FULL, v0 == tgt0)) - 1;
        tag1 = __ffs(__ballot_sync(FULL, v1 == tgt1)) - 1;
        ob0[0] = (lane == tag0) ? 1.0f : 0.0f;
        ob1[0] = (lane == tag1) ? 1.0f : 0.0f;
    }
}

extern "C" void kernel_launch(void* const* d_in, const int* in_sizes, int n_in,
                              void* d_out, int out_size)
{
    const float* pot   = (const float*)d_in[0];
    const float* trans = (const float*)d_in[1];
    float* outp        = (float*)d_out;
    cudaFuncSetAttribute(crf_viterbi_kernel,
                         cudaFuncAttributeMaxDynamicSharedMemorySize, SMEM_DYN_BYTES);
    crf_viterbi_kernel<<<B / (WPC * CPW), WPC * 32, SMEM_DYN_BYTES>>>(pot, trans, outp);
}

// round 11
// speedup vs baseline: 1.0241x; 1.0241x over previous
#include <cuda_runtime.h>
#include <cstdint>

#define B 512
#define T 2048
#define K 32
#define CH 32            // time steps per staged chunk
#define NCH (T / CH)     // 64 chunks
#define WPC 2            // warps per CTA
#define CPW 2            // chains (batches) per warp
#define CHB (CH * K * 4) // 4096
#define FULL 0xffffffffu

#define POT_F (WPC * CPW * 2 * CH * K)
#define M_F   (WPC * CPW * 2 * CH * K)
#define SMEM_DYN_BYTES ((POT_F + M_F + K * K + WPC * CPW * K) * 4)

// m-trace; last 2 chunks per batch never hit gmem
__device__ float g_m[(size_t)B * T * K];

#define ADD2(out, a, b) asm("add.rn.f32x2 %0, %1, %2;" : "=l"(out) : "l"(a), "l"(b))
#define UNPK(lo, hi, v) asm("mov.b64 {%0, %1}, %2;" : "=f"(lo), "=f"(hi) : "l"(v))
#define WSYNC()         __syncwarp()

__device__ __forceinline__ void cp16(uint32_t saddr, const void* gptr) {
    asm volatile("cp.async.cg.shared.global [%0], [%1], 16;" :: "r"(saddr), "l"(gptr));
}
#define CP_COMMIT()  asm volatile("cp.async.commit_group;")
#define CP_WAIT(n)   asm volatile("cp.async.wait_group %0;" :: "n"(n))

__device__ __forceinline__ void bulk_s2g(void* gdst, uint32_t ssrc, uint32_t bytes) {
    asm volatile("cp.async.bulk.global.shared::cta.bulk_group [%0], [%1], %2;"
                 :: "l"(gdst), "r"(ssrc), "r"(bytes) : "memory");
}
#define BULK_COMMIT()    asm volatile("cp.async.bulk.commit_group;")
#define BULK_WAIT_RD(n)  asm volatile("cp.async.bulk.wait_group.read %0;" :: "n"(n))
#define BULK_WAIT(n)     asm volatile("cp.async.bulk.wait_group %0;" :: "n"(n))
#define FENCE_ASYNC()    asm volatile("fence.proxy.async.shared::cta;" ::: "memory")

__global__ void __launch_bounds__(WPC * 32, 1) crf_viterbi_kernel(
    const float* __restrict__ pot,     // [B, T, K]
    const float* __restrict__ trans,   // [K, K]
    float* __restrict__ out)           // [B, T, K] one-hot
{
    extern __shared__ __align__(16) float dyn[];
    float* potBase = dyn;                       // [WPC][CPW][2][CH*K]
    float* mBase   = dyn + POT_F;
    float* trColS  = mBase + M_F;               // trColS[j*K+i] = trans[i][j]
    float* stBase  = trColS + K * K;            // [WPC][CPW][K]

    const int lane = threadIdx.x & 31;
    const int w    = threadIdx.x >> 5;
    const int b0   = (blockIdx.x * WPC + w) * CPW;

    const char* pB0 = (const char*)(pot + (size_t)b0 * T * K);
    const char* pB1 = (const char*)(pot + (size_t)(b0 + 1) * T * K);
    const char* mB0 = (const char*)(g_m + (size_t)b0 * T * K);
    const char* mB1 = (const char*)(g_m + (size_t)(b0 + 1) * T * K);
    float* ob0 = out + (size_t)b0 * T * K + lane;
    float* ob1 = out + (size_t)(b0 + 1) * T * K + lane;

    float* p00 = potBase + ((w * CPW + 0) * 2 + 0) * CH * K;
    float* p01 = potBase + ((w * CPW + 0) * 2 + 1) * CH * K;
    float* p10 = potBase + ((w * CPW + 1) * 2 + 0) * CH * K;
    float* p11 = potBase + ((w * CPW + 1) * 2 + 1) * CH * K;
    float* m00 = mBase + ((w * CPW + 0) * 2 + 0) * CH * K;
    float* m01 = mBase + ((w * CPW + 0) * 2 + 1) * CH * K;
    float* m10 = mBase + ((w * CPW + 1) * 2 + 0) * CH * K;
    float* m11 = mBase + ((w * CPW + 1) * 2 + 1) * CH * K;
    float* st0 = stBase + (w * CPW + 0) * K;
    float* st1 = stBase + (w * CPW + 1) * K;

    const uint32_t pA00 = (uint32_t)__cvta_generic_to_shared(p00);
    const uint32_t pA01 = (uint32_t)__cvta_generic_to_shared(p01);
    const uint32_t pA10 = (uint32_t)__cvta_generic_to_shared(p10);
    const uint32_t pA11 = (uint32_t)__cvta_generic_to_shared(p11);
    const uint32_t mA00 = (uint32_t)__cvta_generic_to_shared(m00);
    const uint32_t mA01 = (uint32_t)__cvta_generic_to_shared(m01);
    const uint32_t mA10 = (uint32_t)__cvta_generic_to_shared(m10);
    const uint32_t mA11 = (uint32_t)__cvta_generic_to_shared(m11);

    // packed transition column `lane` (shared by both chains)
    unsigned long long tj2[16];
#pragma unroll
    for (int q = 0; q < 16; q++) {
        float lo = __ldg(trans + (2 * q) * K + lane);
        float hi = __ldg(trans + (2 * q + 1) * K + lane);
        asm("mov.b64 %0, {%1, %2};" : "=l"(tj2[q]) : "f"(lo), "f"(hi));
    }
    if (w == 0) {
#pragma unroll
        for (int i = 0; i < K; i++) trColS[lane * K + i] = trans[i * K + lane];
    }
    __syncthreads();

#define STAGE_POT(c, db0, db1) do {                                            \
        const char* s0_ = pB0 + (size_t)(c) * CHB;                             \
        const char* s1_ = pB1 + (size_t)(c) * CHB;                             \
        _Pragma("unroll")                                                      \
        for (int i = 0; i < 8; i++) cp16((db0) + lane*16 + i*512, s0_ + lane*16 + i*512); \
        _Pragma("unroll")                                                      \
        for (int i = 0; i < 8; i++) cp16((db1) + lane*16 + i*512, s1_ + lane*16 + i*512); \
    } while (0)

    // ---- stage forward chunks 0 and 1 for both chains ----
    STAGE_POT(0, pA00, pA10); CP_COMMIT();
    STAGE_POT(1, pA01, pA11); CP_COMMIT();
    CP_WAIT(1);
    WSYNC();

    float s0 = p00[lane], s1 = p10[lane];       // s(0)
    const float pot0_0 = s0, pot0_1 = s1;
    float mlast0 = 0.0f, mlast1 = 0.0f;

// register-lean fused step: each q-slice reduced immediately (4 floats -> 1),
// chains A and B interleaved per-q so the scheduler can overlap them.
#define FSTEP2(r, pc0, pc1, mr0, mr1) do {                                     \
        const float pcur0 = (pc0)[(r) * K + lane];                             \
        const float pcur1 = (pc1)[(r) * K + lane];                             \
        st0[lane] = s0;  st1[lane] = s1;                                       \
        const ulonglong2* sp0 = (const ulonglong2*)st0;                        \
        const ulonglong2* sp1 = (const ulonglong2*)st1;                        \
        float ta[8], tb[8];                                                    \
        _Pragma("unroll")                                                      \
        for (int q = 0; q < 8; q++) {                                          \
            ulonglong2 ra = sp0[q];                                            \
            unsigned long long x0, y0;                                         \
            ADD2(x0, ra.x, tj2[2*q]);  ADD2(y0, ra.y, tj2[2*q+1]);             \
            ulonglong2 rb = sp1[q];                                            \
            unsigned long long x1, y1;                                         \
            ADD2(x1, rb.x, tj2[2*q]);  ADD2(y1, rb.y, tj2[2*q+1]);             \
            float l0, h0, l1, h1;                                              \
            UNPK(l0, h0, x0); UNPK(l1, h1, y0);                                \
            ta[q] = fmaxf(fmaxf(l0, h0), fmaxf(l1, h1));                       \
            UNPK(l0, h0, x1); UNPK(l1, h1, y1);                                \
            tb[q] = fmaxf(fmaxf(l0, h0), fmaxf(l1, h1));                       \
        }                                                                      \
        _Pragma("unroll")                                                      \
        for (int q = 0; q < 4; q++) { ta[q] = fmaxf(ta[2*q], ta[2*q+1]);       \
                                      tb[q] = fmaxf(tb[2*q], tb[2*q+1]); }     \
        const float ma = fmaxf(fmaxf(ta[0], ta[1]), fmaxf(ta[2], ta[3]));      \
        const float mb = fmaxf(fmaxf(tb[0], tb[1]), fmaxf(tb[2], tb[3]));      \
        (mr0)[(r) * K + lane] = ma;                                            \
        (mr1)[(r) * K + lane] = mb;                                            \
        s0 = ma + pcur0;  s1 = mb + pcur1;                                     \
        mlast0 = ma;      mlast1 = mb;                                         \
    } while (0)

    // ================= forward =================
    // chunk 0 (rows 1..CH-1), peeled
    {
#pragma unroll 4
        for (int r = 1; r < CH; r++) FSTEP2(r, p00, p10, m00, m10);
        WSYNC();
        FENCE_ASYNC();
        if (lane == 0) {
            bulk_s2g((void*)mB0, mA00, CHB);
            bulk_s2g((void*)mB1, mA10, CHB);
            BULK_COMMIT();
            BULK_WAIT_RD(1);
        }
        STAGE_POT(2, pA00, pA10);
        CP_COMMIT();
        CP_WAIT(1);
        WSYNC();
    }
    for (int c = 1; c < NCH; c++) {
        const float* pc0 = (c & 1) ? p01 : p00;
        const float* pc1 = (c & 1) ? p11 : p10;
        float* mr0 = (c & 1) ? m01 : m00;
        float* mr1 = (c & 1) ? m11 : m10;
#pragma unroll 4
        for (int r = 0; r < CH; r++) FSTEP2(r, pc0, pc1, mr0, mr1);
        WSYNC();
        if (c <= NCH - 3) {
            FENCE_ASYNC();
            if (lane == 0) {
                bulk_s2g((void*)(mB0 + (size_t)c * CHB), (c & 1) ? mA01 : mA00, CHB);
                bulk_s2g((void*)(mB1 + (size_t)c * CHB), (c & 1) ? mA11 : mA10, CHB);
                BULK_COMMIT();
                BULK_WAIT_RD(1);
            }
        }
        if (c + 2 < NCH) {
            STAGE_POT(c + 2, ((c & 1) == 0) ? pA00 : pA01, ((c & 1) == 0) ? pA10 : pA11);
            CP_COMMIT();
            CP_WAIT(1);
            WSYNC();
        } else if (c + 1 < NCH) {
            CP_WAIT(0);
            WSYNC();
        }
    }

    // ---- final tags ----
    float mm0 = s0, mm1 = s1;
#pragma unroll
    for (int off = 16; off; off >>= 1) {
        mm0 = fmaxf(mm0, __shfl_xor_sync(FULL, mm0, off));
        mm1 = fmaxf(mm1, __shfl_xor_sync(FULL, mm1, off));
    }
    int tag0 = __ffs(__ballot_sync(FULL, s0 == mm0)) - 1;
    int tag1 = __ffs(__ballot_sync(FULL, s1 == mm1)) - 1;
    ob0[(size_t)(T - 1) * K] = (lane == tag0) ? 1.0f : 0.0f;
    ob1[(size_t)(T - 1) * K] = (lane == tag1) ? 1.0f : 0.0f;

    if (lane == 0) BULK_WAIT(0);
    WSYNC();

    // ================= backtrack (last 2 chunks resident) =================
    float mcur0 = mlast0, mcur1 = mlast1;

#define BSTEP2(tp, r, mc0, pc0, mc1, pc1) do {                                 \
        const float tgt0 = __shfl_sync(FULL, mcur0, tag0);                     \
        const float tgt1 = __shfl_sync(FULL, mcur1, tag1);                     \
        const float tv0 = trColS[tag0 * K + lane];                             \
        const float tv1 = trColS[tag1 * K + lane];                             \
        const float mp0 = (mc0)[(r) * K + lane];                               \
        const float mp1 = (mc1)[(r) * K + lane];                               \
        const float pp0 = (pc0)[(r) * K + lane];                               \
        const float pp1 = (pc1)[(r) * K + lane];                               \
        const float v0 = (mp0 + pp0) + tv0;                                    \
        const float v1 = (mp1 + pp1) + tv1;                                    \
        const unsigned k0 = __ballot_sync(FULL, v0 == tgt0);                   \
        const unsigned k1 = __ballot_sync(FULL, v1 == tgt1);                   \
        tag0 = __ffs(k0) - 1;  tag1 = __ffs(k1) - 1;                           \
        ob0[(size_t)(tp) * K] = (lane == tag0) ? 1.0f : 0.0f;                  \
        ob1[(size_t)(tp) * K] = (lane == tag1) ? 1.0f : 0.0f;                  \
        mcur0 = mp0;  mcur1 = mp1;                                             \
    } while (0)

#define STAGE_BT(c) do {                                                       \
        const uint32_t md0 = (((c) & 1) == 0) ? mA00 : mA01;                   \
        const uint32_t md1 = (((c) & 1) == 0) ? mA10 : mA11;                   \
        const uint32_t pd0 = (((c) & 1) == 0) ? pA00 : pA01;                   \
        const uint32_t pd1 = (((c) & 1) == 0) ? pA10 : pA11;                   \
        const char* gm0 = mB0 + (size_t)((c) - 2) * CHB;                       \
        const char* gm1 = mB1 + (size_t)((c) - 2) * CHB;                       \
        const char* gp0 = pB0 + (size_t)((c) - 2) * CHB;                       \
        const char* gp1 = pB1 + (size_t)((c) - 2) * CHB;                       \
        _Pragma("unroll")                                                      \
        for (int i = 0; i < 8; i++) {                                          \
            cp16(md0 + lane*16 + i*512, gm0 + lane*16 + i*512);                \
            cp16(md1 + lane*16 + i*512, gm1 + lane*16 + i*512);                \
            cp16(pd0 + lane*16 + i*512, gp0 + lane*16 + i*512);                \
            cp16(pd1 + lane*16 + i*512, gp1 + lane*16 + i*512);                \
        }                                                                      \
        CP_COMMIT();                                                           \
        CP_WAIT(1);                                                            \
        WSYNC();                                                               \
    } while (0)

    // chunk NCH-1 (buf 1): rows CH-2..0
    {
#pragma unroll 4
        for (int r = CH - 2; r >= 0; r--) BSTEP2((NCH - 1) * CH + r, r, m01, p01, m11, p11);
        STAGE_BT(NCH - 1);
    }
    for (int c = NCH - 2; c >= 1; c--) {
        const float* mc0 = (c & 1) ? m01 : m00;
        const float* mc1 = (c & 1) ? m11 : m10;
        const float* pc0 = (c & 1) ? p01 : p00;
        const float* pc1 = (c & 1) ? p11 : p10;
#pragma unroll 4
        for (int r = CH - 1; r >= 0; r--) BSTEP2(c * CH + r, r, mc0, pc0, mc1, pc1);
        if (c >= 2) {
            STAGE_BT(c);
        } else {
            CP_WAIT(0);
            WSYNC();
        }
    }
    // chunk 0: rows CH-1..1
    {
#pragma unroll 4
        for (int r = CH - 1; r >= 1; r--) BSTEP2(r, r, m00, p00, m10, p10);
    }
    // last step: t=1 -> tag(0)
    {
        const float tgt0 = __shfl_sync(FULL, mcur0, tag0);
        const float tgt1 = __shfl_sync(FULL, mcur1, tag1);
        const float v0 = pot0_0 + trColS[tag0 * K + lane];
        const float v1 = pot0_1 + trColS[tag1 * K + lane];
        tag0 = __ffs(__ballot_sync(FULL, v0 == tgt0)) - 1;
        tag1 = __ffs(__ballot_sync(FULL, v1 == tgt1)) - 1;
        ob0[0] = (lane == tag0) ? 1.0f : 0.0f;
        ob1[0] = (lane == tag1) ? 1.0f : 0.0f;
    }
}

extern "C" void kernel_launch(void* const* d_in, const int* in_sizes, int n_in,
                              void* d_out, int out_size)
{
    const float* pot   = (const float*)d_in[0];
    const float* trans = (const float*)d_in[1];
    float* outp        = (float*)d_out;
    cudaFuncSetAttribute(crf_viterbi_kernel,
                         cudaFuncAttributeMaxDynamicSharedMemorySize, SMEM_DYN_BYTES);
    crf_viterbi_kernel<<<B / (WPC * CPW), WPC * 32, SMEM_DYN_BYTES>>>(pot, trans, outp);
}

// round 12
// speedup vs baseline: 1.1293x; 1.1027x over previous
#include <cuda_runtime.h>
#include <cstdint>

#define B 512
#define T 2048
#define K 32
#define CH 32            // time steps per staged chunk
#define NCH (T / CH)     // 64 chunks
#define WPC 8            // warps (batches) per CTA -> 2 warps per SMSP
#define CHB (CH * K * 4) // chunk bytes = 4096
#define FULL 0xffffffffu

// dynamic smem (floats): pot[WPC][2][CH*K] | m[WPC][2][CH*K] | trCol[K*K] | st[WPC][K]
#define POT_F (WPC * 2 * CH * K)
#define M_F   (WPC * 2 * CH * K)
#define SMEM_DYN_BYTES ((POT_F + M_F + K * K + WPC * K) * 4)

// m-trace; last 2 chunks per batch never hit gmem
__device__ float g_m[(size_t)B * T * K];

#define ADD2(out, a, b) asm("add.rn.f32x2 %0, %1, %2;" : "=l"(out) : "l"(a), "l"(b))
#define UNPK(lo, hi, v) asm("mov.b64 {%0, %1}, %2;" : "=f"(lo), "=f"(hi) : "l"(v))
#define WSYNC()         __syncwarp()

__device__ __forceinline__ void cp16(uint32_t saddr, const void* gptr) {
    asm volatile("cp.async.cg.shared.global [%0], [%1], 16;" :: "r"(saddr), "l"(gptr));
}
#define CP_COMMIT()  asm volatile("cp.async.commit_group;")
#define CP_WAIT(n)   asm volatile("cp.async.wait_group %0;" :: "n"(n))

__device__ __forceinline__ void bulk_s2g(void* gdst, uint32_t ssrc, uint32_t bytes) {
    asm volatile("cp.async.bulk.global.shared::cta.bulk_group [%0], [%1], %2;"
                 :: "l"(gdst), "r"(ssrc), "r"(bytes) : "memory");
}
#define BULK_COMMIT()    asm volatile("cp.async.bulk.commit_group;")
#define BULK_WAIT_RD(n)  asm volatile("cp.async.bulk.wait_group.read %0;" :: "n"(n))
#define BULK_WAIT(n)     asm volatile("cp.async.bulk.wait_group %0;" :: "n"(n))
#define FENCE_ASYNC()    asm volatile("fence.proxy.async.shared::cta;" ::: "memory")

__global__ void __launch_bounds__(WPC * 32, 1) crf_viterbi_kernel(
    const float* __restrict__ pot,     // [B, T, K]
    const float* __restrict__ trans,   // [K, K]
    float* __restrict__ out)           // [B, T, K] one-hot
{
    extern __shared__ __align__(16) float dyn[];
    float* potBase = dyn;
    float* mBase   = dyn + POT_F;
    float* trColS  = mBase + M_F;              // trColS[j*K+i] = trans[i][j]
    float* stBase  = trColS + K * K;

    const int lane = threadIdx.x & 31;
    const int w    = threadIdx.x >> 5;
    const int b    = blockIdx.x * WPC + w;

    const char* pB = (const char*)(pot + (size_t)b * T * K);
    const char* mB = (const char*)(g_m + (size_t)b * T * K);
    float* ob      = out + (size_t)b * T * K + lane;

    float* potW0 = potBase + (w * 2 + 0) * CH * K;
    float* potW1 = potBase + (w * 2 + 1) * CH * K;
    float* mW0   = mBase + (w * 2 + 0) * CH * K;
    float* mW1   = mBase + (w * 2 + 1) * CH * K;
    float* stW   = stBase + w * K;
    const uint32_t potA0 = (uint32_t)__cvta_generic_to_shared(potW0);
    const uint32_t potA1 = (uint32_t)__cvta_generic_to_shared(potW1);
    const uint32_t mA0   = (uint32_t)__cvta_generic_to_shared(mW0);
    const uint32_t mA1   = (uint32_t)__cvta_generic_to_shared(mW1);

    // packed transition column `lane`
    unsigned long long tj2[16];
#pragma unroll
    for (int q = 0; q < 16; q++) {
        float lo = __ldg(trans + (2 * q) * K + lane);
        float hi = __ldg(trans + (2 * q + 1) * K + lane);
        asm("mov.b64 %0, {%1, %2};" : "=l"(tj2[q]) : "f"(lo), "f"(hi));
    }
    if (w == 0) {
#pragma unroll
        for (int i = 0; i < K; i++) trColS[lane * K + i] = trans[i * K + lane];
    }
    __syncthreads();

    // ---- stage forward chunks 0 and 1 (8 x cp16 per lane per chunk) ----
#pragma unroll
    for (int i = 0; i < 8; i++)
        cp16(potA0 + lane * 16 + i * 512, pB + lane * 16 + i * 512);
    CP_COMMIT();
#pragma unroll
    for (int i = 0; i < 8; i++)
        cp16(potA1 + lane * 16 + i * 512, pB + CHB + lane * 16 + i * 512);
    CP_COMMIT();
    CP_WAIT(1);
    WSYNC();

    float s = potW0[lane];            // s(0) = pot(0)
    const float pot0 = s;
    float mlast = 0.0f;

// one forward DP step (values only); same-warp STS->LDS is in program order
#define FSTEP(r, pc, mrow) do {                                           \
        const float pcur = (pc)[(r) * K + lane];                          \
        stW[lane] = s;                                                    \
        const ulonglong2* sp = (const ulonglong2*)stW;                    \
        unsigned long long v2[16];                                        \
        _Pragma("unroll")                                                 \
        for (int q = 0; q < 8; q++) {                                     \
            ulonglong2 rr = sp[q];                                        \
            ADD2(v2[2 * q],     rr.x, tj2[2 * q]);                        \
            ADD2(v2[2 * q + 1], rr.y, tj2[2 * q + 1]);                    \
        }                                                                 \
        float m0[16];                                                     \
        _Pragma("unroll")                                                 \
        for (int q = 0; q < 16; q++) {                                    \
            float lo, hi; UNPK(lo, hi, v2[q]);                            \
            m0[q] = fmaxf(lo, hi);                                        \
        }                                                                 \
        float m1[8];                                                      \
        _Pragma("unroll")                                                 \
        for (int q = 0; q < 8; q++) m1[q] = fmaxf(m0[2*q], m0[2*q+1]);    \
        float m2[4];                                                      \
        _Pragma("unroll")                                                 \
        for (int q = 0; q < 4; q++) m2[q] = fmaxf(m1[2*q], m1[2*q+1]);    \
        const float m = fmaxf(fmaxf(m2[0], m2[1]), fmaxf(m2[2], m2[3]));  \
        (mrow)[(r) * K + lane] = m;                                       \
        s = m + pcur;                                                     \
        mlast = m;                                                        \
    } while (0)

    // ================= forward =================
    {
#pragma unroll 8
        for (int r = 1; r < CH; r++) FSTEP(r, potW0, mW0);
        WSYNC();
        FENCE_ASYNC();
        if (lane == 0) {
            bulk_s2g((void*)mB, mA0, CHB);
            BULK_COMMIT();
            BULK_WAIT_RD(1);
        }
        const char* src = pB + 2 * (size_t)CHB;
#pragma unroll
        for (int i = 0; i < 8; i++)
            cp16(potA0 + lane * 16 + i * 512, src + lane * 16 + i * 512);
        CP_COMMIT();
        CP_WAIT(1);
        WSYNC();
    }
    for (int c = 1; c < NCH; c++) {
        const float* pc = (c & 1) ? potW1 : potW0;
        float* mrow     = (c & 1) ? mW1 : mW0;
#pragma unroll 8
        for (int r = 0; r < CH; r++) FSTEP(r, pc, mrow);
        WSYNC();
        if (c <= NCH - 3) {
            FENCE_ASYNC();
            if (lane == 0) {
                bulk_s2g((void*)(mB + (size_t)c * CHB), (c & 1) ? mA1 : mA0, CHB);
                BULK_COMMIT();
                BULK_WAIT_RD(1);
            }
        }
        if (c + 2 < NCH) {
            const uint32_t dst = ((c & 1) == 0) ? potA0 : potA1;
            const char* src = pB + (size_t)(c + 2) * CHB;
#pragma unroll
            for (int i = 0; i < 8; i++)
                cp16(dst + lane * 16 + i * 512, src + lane * 16 + i * 512);
            CP_COMMIT();
            CP_WAIT(1);
            WSYNC();
        } else if (c + 1 < NCH) {
            CP_WAIT(0);
            WSYNC();
        }
    }

    // ---- final tag ----
    float mm = s;
#pragma unroll
    for (int off = 16; off; off >>= 1) mm = fmaxf(mm, __shfl_xor_sync(FULL, mm, off));
    int tag = __ffs(__ballot_sync(FULL, s == mm)) - 1;
    ob[(size_t)(T - 1) * K] = (lane == tag) ? 1.0f : 0.0f;

    if (lane == 0) BULK_WAIT(0);
    WSYNC();

    // ================= backtrack (chunks NCH-1, NCH-2 resident) =================
    float mcur = mlast;

#define BSTEP(tp, r, mc, pcS) do {                                        \
        const float target = __shfl_sync(FULL, mcur, tag);                \
        const float tv = trColS[tag * K + lane];                          \
        const float mprev = (mc)[(r) * K + lane];                         \
        const float pprev = (pcS)[(r) * K + lane];                        \
        const float v = (mprev + pprev) + tv;                             \
        const unsigned msk = __ballot_sync(FULL, v == target);            \
        tag = __ffs(msk) - 1;                                             \
        ob[(size_t)(tp) * K] = (lane == tag) ? 1.0f : 0.0f;               \
        mcur = mprev;                                                     \
    } while (0)

#define STAGE_BT(c) do {                                                  \
        const uint32_t md = (((c) & 1) == 0) ? mA0 : mA1;                 \
        const uint32_t pd = (((c) & 1) == 0) ? potA0 : potA1;             \
        const char* gm = mB + (size_t)((c) - 2) * CHB;                    \
        const char* gp = pB + (size_t)((c) - 2) * CHB;                    \
        _Pragma("unroll")                                                 \
        for (int i = 0; i < 8; i++) cp16(md + lane*16 + i*512, gm + lane*16 + i*512); \
        _Pragma("unroll")                                                 \
        for (int i = 0; i < 8; i++) cp16(pd + lane*16 + i*512, gp + lane*16 + i*512); \
        CP_COMMIT();                                                      \
        CP_WAIT(1);                                                       \
        WSYNC();                                                          \
    } while (0)

    // chunk NCH-1: rows CH-2..0
    {
#pragma unroll 8
        for (int r = CH - 2; r >= 0; r--) BSTEP((NCH - 1) * CH + r, r, mW1, potW1);
        STAGE_BT(NCH - 1);
    }
    for (int c = NCH - 2; c >= 1; c--) {
        const float* mc  = (c & 1) ? mW1 : mW0;
        const float* pcS = (c & 1) ? potW1 : potW0;
#pragma unroll 8
        for (int r = CH - 1; r >= 0; r--) BSTEP(c * CH + r, r, mc, pcS);
        if (c >= 2) {
            STAGE_BT(c);
        } else {
            CP_WAIT(0);
            WSYNC();
        }
    }
    // chunk 0: rows CH-1..1
    {
#pragma unroll 8
        for (int r = CH - 1; r >= 1; r--) BSTEP(r, r, mW0, potW0);
    }
    // last step: t=1 -> tag(0)
    {
        const float target = __shfl_sync(FULL, mcur, tag);
        const float tv = trColS[tag * K + lane];
        const float v = pot0 + tv;
        tag = __ffs(__ballot_sync(FULL, v == target)) - 1;
        ob[0] = (lane == tag) ? 1.0f : 0.0f;
    }
}

extern "C" void kernel_launch(void* const* d_in, const int* in_sizes, int n_in,
                              void* d_out, int out_size)
{
    const float* pot   = (const float*)d_in[0];
    const float* trans = (const float*)d_in[1];
    float* outp        = (float*)d_out;
    cudaFuncSetAttribute(crf_viterbi_kernel,
                         cudaFuncAttributeMaxDynamicSharedMemorySize, SMEM_DYN_BYTES);
    crf_viterbi_kernel<<<B / WPC, WPC * 32, SMEM_DYN_BYTES>>>(pot, trans, outp);
}

// round 13
// speedup vs baseline: 1.4587x; 1.2917x over previous
#include <cuda_runtime.h>
#include <cstdint>

#define B 512
#define T 2048
#define K 32
#define CH 64            // time steps per staged chunk
#define NCH (T / CH)     // 32 chunks
#define WPC 4            // warps (batches) per CTA -> 1 per SMSP, grid=128 (1 CTA/SM)
#define CHB (CH * K * 4) // 8192
#define FULL 0xffffffffu

#define POT_F (WPC * 2 * CH * K)
#define M_F   (WPC * 2 * CH * K)
#define SMEM_DYN_BYTES ((POT_F + M_F + K * K + WPC * K) * 4)

// m-trace; last 2 chunks per batch never hit gmem
__device__ float g_m[(size_t)B * T * K];

#define WSYNC()         __syncwarp()

__device__ __forceinline__ void cp16(uint32_t saddr, const void* gptr) {
    asm volatile("cp.async.cg.shared.global [%0], [%1], 16;" :: "r"(saddr), "l"(gptr));
}
#define CP_COMMIT()  asm volatile("cp.async.commit_group;")
#define CP_WAIT(n)   asm volatile("cp.async.wait_group %0;" :: "n"(n))

__device__ __forceinline__ void bulk_s2g(void* gdst, uint32_t ssrc, uint32_t bytes) {
    asm volatile("cp.async.bulk.global.shared::cta.bulk_group [%0], [%1], %2;"
                 :: "l"(gdst), "r"(ssrc), "r"(bytes) : "memory");
}
#define BULK_COMMIT()    asm volatile("cp.async.bulk.commit_group;")
#define BULK_WAIT_RD(n)  asm volatile("cp.async.bulk.wait_group.read %0;" :: "n"(n))
#define BULK_WAIT(n)     asm volatile("cp.async.bulk.wait_group %0;" :: "n"(n))
#define FENCE_ASYNC()    asm volatile("fence.proxy.async.shared::cta;" ::: "memory")

__global__ void __launch_bounds__(WPC * 32, 1) crf_viterbi_kernel(
    const float* __restrict__ pot,     // [B, T, K]
    const float* __restrict__ trans,   // [K, K]
    float* __restrict__ out)           // [B, T, K] one-hot
{
    extern __shared__ __align__(16) float dyn[];
    float* potBase = dyn;
    float* mBase   = dyn + POT_F;
    float* trColS  = mBase + M_F;              // trColS[j*K+i] = trans[i][j]
    float* stBase  = trColS + K * K;

    const int lane = threadIdx.x & 31;
    const int w    = threadIdx.x >> 5;
    const int b    = blockIdx.x * WPC + w;

    const char* pB = (const char*)(pot + (size_t)b * T * K);
    const char* mB = (const char*)(g_m + (size_t)b * T * K);
    float* ob      = out + (size_t)b * T * K + lane;

    float* potW0 = potBase + (w * 2 + 0) * CH * K;
    float* potW1 = potBase + (w * 2 + 1) * CH * K;
    float* mW0   = mBase + (w * 2 + 0) * CH * K;
    float* mW1   = mBase + (w * 2 + 1) * CH * K;
    float* stW   = stBase + w * K;
    const uint32_t potA0 = (uint32_t)__cvta_generic_to_shared(potW0);
    const uint32_t potA1 = (uint32_t)__cvta_generic_to_shared(potW1);
    const uint32_t mA0   = (uint32_t)__cvta_generic_to_shared(mW0);
    const uint32_t mA1   = (uint32_t)__cvta_generic_to_shared(mW1);

    // scalar transition column `lane`: tj[i] = trans[i][lane]
    float tj[K];
#pragma unroll
    for (int i = 0; i < K; i++) tj[i] = __ldg(trans + i * K + lane);

    if (w == 0) {
#pragma unroll
        for (int i = 0; i < K; i++) trColS[lane * K + i] = trans[i * K + lane];
    }
    __syncthreads();

    // ---- stage forward chunks 0 and 1 (16 x cp16 per lane per chunk) ----
#pragma unroll
    for (int i = 0; i < 16; i++)
        cp16(potA0 + lane * 16 + i * 512, pB + lane * 16 + i * 512);
    CP_COMMIT();
#pragma unroll
    for (int i = 0; i < 16; i++)
        cp16(potA1 + lane * 16 + i * 512, pB + CHB + lane * 16 + i * 512);
    CP_COMMIT();
    CP_WAIT(1);
    WSYNC();

    float s = potW0[lane];            // s(0) = pot(0)
    const float pot0 = s;
    float mlast = 0.0f;

// unpacked forward step: 8x LDS.128 (float4 broadcast), 32 FADD, 31 FMNMX,
// arrival-ordered running combine (fmax reassociation is exact).
#define FSTEP(r, pc, mrow) do {                                           \
        const float pcur = (pc)[(r) * K + lane];                          \
        stW[lane] = s;                                                    \
        const float4* sp = (const float4*)stW;                           \
        float run0, run1;                                                 \
        {   float4 q0 = sp[0];                                            \
            float a0 = q0.x + tj[0], a1 = q0.y + tj[1];                   \
            float a2 = q0.z + tj[2], a3 = q0.w + tj[3];                   \
            run0 = fmaxf(fmaxf(a0, a1), fmaxf(a2, a3)); }                 \
        {   float4 q1 = sp[1];                                            \
            float a0 = q1.x + tj[4], a1 = q1.y + tj[5];                   \
            float a2 = q1.z + tj[6], a3 = q1.w + tj[7];                   \
            run1 = fmaxf(fmaxf(a0, a1), fmaxf(a2, a3)); }                 \
        _Pragma("unroll")                                                 \
        for (int q = 2; q < 8; q += 2) {                                  \
            float4 qa = sp[q];                                            \
            float a0 = qa.x + tj[4*q+0], a1 = qa.y + tj[4*q+1];           \
            float a2 = qa.z + tj[4*q+2], a3 = qa.w + tj[4*q+3];           \
            run0 = fmaxf(run0, fmaxf(fmaxf(a0, a1), fmaxf(a2, a3)));      \
            float4 qb = sp[q + 1];                                        \
            float b0 = qb.x + tj[4*q+4], b1 = qb.y + tj[4*q+5];           \
            float b2 = qb.z + tj[4*q+6], b3 = qb.w + tj[4*q+7];           \
            run1 = fmaxf(run1, fmaxf(fmaxf(b0, b1), fmaxf(b2, b3)));      \
        }                                                                 \
        const float m = fmaxf(run0, run1);                                \
        (mrow)[(r) * K + lane] = m;                                       \
        s = m + pcur;                                                     \
        mlast = m;                                                        \
    } while (0)

    // ================= forward =================
    {
#pragma unroll 8
        for (int r = 1; r < CH; r++) FSTEP(r, potW0, mW0);
        WSYNC();
        FENCE_ASYNC();
        if (lane == 0) {
            bulk_s2g((void*)mB, mA0, CHB);
            BULK_COMMIT();
            BULK_WAIT_RD(1);
        }
        const char* src = pB + 2 * (size_t)CHB;
#pragma unroll
        for (int i = 0; i < 16; i++)
            cp16(potA0 + lane * 16 + i * 512, src + lane * 16 + i * 512);
        CP_COMMIT();
        CP_WAIT(1);
        WSYNC();
    }
    for (int c = 1; c < NCH; c++) {
        const float* pc = (c & 1) ? potW1 : potW0;
        float* mrow     = (c & 1) ? mW1 : mW0;
#pragma unroll 8
        for (int r = 0; r < CH; r++) FSTEP(r, pc, mrow);
        WSYNC();
        if (c <= NCH - 3) {
            FENCE_ASYNC();
            if (lane == 0) {
                bulk_s2g((void*)(mB + (size_t)c * CHB), (c & 1) ? mA1 : mA0, CHB);
                BULK_COMMIT();
                BULK_WAIT_RD(1);
            }
        }
        if (c + 2 < NCH) {
            const uint32_t dst = ((c & 1) == 0) ? potA0 : potA1;
            const char* src = pB + (size_t)(c + 2) * CHB;
#pragma unroll
            for (int i = 0; i < 16; i++)
                cp16(dst + lane * 16 + i * 512, src + lane * 16 + i * 512);
            CP_COMMIT();
            CP_WAIT(1);
            WSYNC();
        } else if (c + 1 < NCH) {
            CP_WAIT(0);
            WSYNC();
        }
    }

    // ---- final tag ----
    float mm = s;
#pragma unroll
    for (int off = 16; off; off >>= 1) mm = fmaxf(mm, __shfl_xor_sync(FULL, mm, off));
    int tag = __ffs(__ballot_sync(FULL, s == mm)) - 1;
    ob[(size_t)(T - 1) * K] = (lane == tag) ? 1.0f : 0.0f;

    if (lane == 0) BULK_WAIT(0);
    WSYNC();

    // ================= backtrack (chunks NCH-1, NCH-2 resident) =================
    float mcur = mlast;

#define BSTEP(tp, r, mc, pcS) do {                                        \
        const float target = __shfl_sync(FULL, mcur, tag);                \
        const float tv = trColS[tag * K + lane];                          \
        const float mprev = (mc)[(r) * K + lane];                         \
        const float pprev = (pcS)[(r) * K + lane];                        \
        const float v = (mprev + pprev) + tv;                             \
        const unsigned msk = __ballot_sync(FULL, v == target);            \
        tag = __ffs(msk) - 1;                                             \
        ob[(size_t)(tp) * K] = (lane == tag) ? 1.0f : 0.0f;               \
        mcur = mprev;                                                     \
    } while (0)

#define STAGE_BT(c) do {                                                  \
        const uint32_t md = (((c) & 1) == 0) ? mA0 : mA1;                 \
        const uint32_t pd = (((c) & 1) == 0) ? potA0 : potA1;             \
        const char* gm = mB + (size_t)((c) - 2) * CHB;                    \
        const char* gp = pB + (size_t)((c) - 2) * CHB;                    \
        _Pragma("unroll")                                                 \
        for (int i = 0; i < 16; i++) cp16(md + lane*16 + i*512, gm + lane*16 + i*512); \
        _Pragma("unroll")                                                 \
        for (int i = 0; i < 16; i++) cp16(pd + lane*16 + i*512, gp + lane*16 + i*512); \
        CP_COMMIT();                                                      \
        CP_WAIT(1);                                                       \
        WSYNC();                                                          \
    } while (0)

    // chunk NCH-1: rows CH-2..0
    {
#pragma unroll 8
        for (int r = CH - 2; r >= 0; r--) BSTEP((NCH - 1) * CH + r, r, mW1, potW1);
        STAGE_BT(NCH - 1);
    }
    for (int c = NCH - 2; c >= 1; c--) {
        const float* mc  = (c & 1) ? mW1 : mW0;
        const float* pcS = (c & 1) ? potW1 : potW0;
#pragma unroll 8
        for (int r = CH - 1; r >= 0; r--) BSTEP(c * CH + r, r, mc, pcS);
        if (c >= 2) {
            STAGE_BT(c);
        } else {
            CP_WAIT(0);
            WSYNC();
        }
    }
    // chunk 0: rows CH-1..1
    {
#pragma unroll 8
        for (int r = CH - 1; r >= 1; r--) BSTEP(r, r, mW0, potW0);
    }
    // last step: t=1 -> tag(0)
    {
        const float target = __shfl_sync(FULL, mcur, tag);
        const float tv = trColS[tag * K + lane];
        const float v = pot0 + tv;
        tag = __ffs(__ballot_sync(FULL, v == target)) - 1;
        ob[0] = (lane == tag) ? 1.0f : 0.0f;
    }
}

extern "C" void kernel_launch(void* const* d_in, const int* in_sizes, int n_in,
                              void* d_out, int out_size)
{
    const float* pot   = (const float*)d_in[0];
    const float* trans = (const float*)d_in[1];
    float* outp        = (float*)d_out;
    cudaFuncSetAttribute(crf_viterbi_kernel,
                         cudaFuncAttributeMaxDynamicSharedMemorySize, SMEM_DYN_BYTES);
    crf_viterbi_kernel<<<B / WPC, WPC * 32, SMEM_DYN_BYTES>>>(pot, trans, outp);
}